// round 15
// baseline (speedup 1.0000x reference)
#include <cuda_runtime.h>
#include <cstdint>

// ---------------- problem constants ----------------
#define BATCH 256
#define HW    147456            // 384*384 px per sample
#define NBF   16384             // fine histogram bins (bin = q >> 2)
#define QSCALE 65535.0f
#define SMEM_H (NBF * 4)        // 64 KB dynamic smem for K1 histogram

// target order-statistic ranks (0-based): q*(n-1) = 14745.5 / 132709.5
#define KL 14745
#define KH 132709

// K1 geometry: 2 blocks/sample, 1024 threads, 72 px/thread
#define TPB1   1024
#define BPS1   2
#define PXB1   (HW / BPS1)            // 73728 px per block
#define ITER1  (PXB1 / (TPB1 * 4))    // 18 iterations of 4 px

// K25 geometry: 9 blocks/sample, 1024 threads, 4 float4 (16 px) per thread
#define TPB2   1024
#define BPS2   9
#define F4PT   4                      // 9*1024*4 = 36864 = HW/4

// ---------------- device scratch (static, allocation-free, zero-init) -------
__device__ __align__(16) uint32_t g_xq[BATCH * HW / 2];  // packed u16 means, 75 MB
__device__ __align__(16) int g_hist[BATCH * NBF];        // fine hist (cleaned by K25)
__device__ float2 g_ab[BATCH];                           // loQ, invQ (u16-value units)
__device__ int    g_ready[BATCH];                        // flag (reset by K1)

// ---- K1: stream x, channel-mean, quantize u16, write xq, fine hist ---------
__global__ void __launch_bounds__(TPB1) k1_quant_hist(const float* __restrict__ x) {
    extern __shared__ int sh[];             // NBF bins
    const int s     = blockIdx.x >> 1;
    const int chunk = blockIdx.x & (BPS1 - 1);
    const int t     = threadIdx.x;

    // reset the ready flag for this sample (runs strictly before K25)
    if (chunk == 0 && t == 0) g_ready[s] = 0;

    for (int i = t; i < NBF; i += TPB1) sh[i] = 0;
    __syncthreads();

    const int base = s * HW + chunk * PXB1;
    const float4* __restrict__ xin = (const float4*)x;
    const float third = 1.0f / 3.0f;

#pragma unroll 3
    for (int it = 0; it < ITER1; ++it) {
        int p  = base + it * (TPB1 * 4) + t * 4;
        int f4 = (p * 3) >> 2;
        float4 a = __ldcs(xin + f4 + 0);   // stream x: don't pollute L2
        float4 b = __ldcs(xin + f4 + 1);
        float4 c = __ldcs(xin + f4 + 2);

        uint32_t q0 = min((uint32_t)((a.x + a.y + a.z) * third * QSCALE + 0.5f), 65535u);
        uint32_t q1 = min((uint32_t)((a.w + b.x + b.y) * third * QSCALE + 0.5f), 65535u);
        uint32_t q2 = min((uint32_t)((b.z + b.w + c.x) * third * QSCALE + 0.5f), 65535u);
        uint32_t q3 = min((uint32_t)((c.y + c.z + c.w) * third * QSCALE + 0.5f), 65535u);

        uint2 w; w.x = q0 | (q1 << 16); w.y = q2 | (q3 << 16);
        ((uint2*)g_xq)[p >> 2] = w;        // retain in L2 for K25

        atomicAdd(&sh[q0 >> 2], 1);
        atomicAdd(&sh[q1 >> 2], 1);
        atomicAdd(&sh[q2 >> 2], 1);
        atomicAdd(&sh[q3 >> 2], 1);
    }
    __syncthreads();

    int* gh = &g_hist[s * NBF];
    for (int i = t; i < NBF; i += TPB1) {
        int v = sh[i];
        if (v) atomicAdd(&gh[i], v);       // result unused -> REDG
    }
}

// ---- K25: chunk-0 block scans+interps+publishes; all blocks normalize ------
__global__ void __launch_bounds__(TPB2) k25_scan_norm(float* __restrict__ out) {
    __shared__ int   s_warp[32];
    __shared__ float s_v[4];

    const int s     = blockIdx.x / BPS2;
    const int chunk = blockIdx.x % BPS2;
    const int t     = threadIdx.x;
    const int lane  = t & 31;
    const int wid   = t >> 5;

    if (chunk == 0) {
        // ---- scan the sample's fine histogram, interpolate quantiles ----
        const int CH = NBF / TPB2;          // 16 bins per thread
        int* gh = &g_hist[s * NBF];
        int cnt[CH];
        int local = 0;
#pragma unroll
        for (int j = 0; j < CH / 4; j++) {
            int4 cw = *(int4*)(gh + 4 * (t * (CH / 4) + j));
            cnt[4 * j + 0] = cw.x; cnt[4 * j + 1] = cw.y;
            cnt[4 * j + 2] = cw.z; cnt[4 * j + 3] = cw.w;
            local += cw.x + cw.y + cw.z + cw.w;
        }
#pragma unroll
        for (int j = 0; j < CH / 4; j++)    // self-clean for graph replay
            *(int4*)(gh + 4 * (t * (CH / 4) + j)) = make_int4(0, 0, 0, 0);

        int v = local;
#pragma unroll
        for (int o = 1; o < 32; o <<= 1) {
            int n = __shfl_up_sync(0xFFFFFFFFu, v, o);
            if (lane >= o) v += n;
        }
        if (lane == 31) s_warp[wid] = v;
        __syncthreads();
        if (wid == 0) {
            int wv = s_warp[lane];
#pragma unroll
            for (int o = 1; o < 32; o <<= 1) {
                int n = __shfl_up_sync(0xFFFFFFFFu, wv, o);
                if (lane >= o) wv += n;
            }
            s_warp[lane] = wv;
        }
        __syncthreads();
        int cum = (v - local) + (wid ? s_warp[wid - 1] : 0);

        const int targets[4] = {KL, KL + 1, KH, KH + 1};
        const int base = t * CH;
        const float BW = 65536.0f / (float)NBF;   // 4.0 u16-units per bin
#pragma unroll
        for (int i = 0; i < CH; i++) {
            int c = cnt[i];
#pragma unroll
            for (int k = 0; k < 4; k++) {
                int r = targets[k];
                if (cum <= r && r < cum + c)
                    s_v[k] = ((float)(base + i) + ((float)(r - cum) + 0.5f) / (float)c) * BW;
            }
            cum += c;
        }
        __syncthreads();

        if (t == 0) {
            float loQ = 0.5f * (s_v[0] + s_v[1]);
            float hiQ = 0.5f * (s_v[2] + s_v[3]);
            float rngQ = fmaxf(hiQ - loQ, 1e-6f * QSCALE);
            g_ab[s] = make_float2(loQ, 1.0f / rngQ);
            __threadfence();                          // release g_ab
            *((volatile int*)&g_ready[s]) = 1;        // publish
        }
        __syncthreads();
    } else {
        // ---- wait for this sample's chunk-0 block (always co-resident) ----
        if (t == 0) {
            while (*((volatile int*)&g_ready[s]) == 0) __nanosleep(128);
        }
        __syncthreads();
        __threadfence();                              // acquire g_ab
    }

    float2 ab = g_ab[s];
    const float loQ  = ab.x;
    const float invQ = ab.y;

    // ---- normalize + clip; xq read L2-hot, streamed output ----
    const uint2* __restrict__ xq2 =
        (const uint2*)g_xq + (size_t)s * (HW / 4) + chunk * (TPB2 * F4PT);
    float4* __restrict__ o4 =
        (float4*)out + (size_t)s * (HW / 4) + chunk * (TPB2 * F4PT);

#pragma unroll
    for (int k = 0; k < F4PT; k++) {
        uint2 w = __ldcs(xq2 + k * TPB2 + t);   // last use of xq
        float4 r;
        r.x = __saturatef(((float)(w.x & 0xFFFFu) - loQ) * invQ);
        r.y = __saturatef(((float)(w.x >> 16)     - loQ) * invQ);
        r.z = __saturatef(((float)(w.y & 0xFFFFu) - loQ) * invQ);
        r.w = __saturatef(((float)(w.y >> 16)     - loQ) * invQ);
        __stcs(o4 + k * TPB2 + t, r);
    }
}

// ---------------- launch ----------------
extern "C" void kernel_launch(void* const* d_in, const int* in_sizes, int n_in,
                              void* d_out, int out_size) {
    const float* x = (const float*)d_in[0];
    float* out = (float*)d_out;

    cudaFuncSetAttribute(k1_quant_hist, cudaFuncAttributeMaxDynamicSharedMemorySize, SMEM_H);
    k1_quant_hist<<<BATCH * BPS1, TPB1, SMEM_H>>>(x);
    k25_scan_norm<<<BATCH * BPS2, TPB2>>>(out);
}

// round 16
// speedup vs baseline: 1.8683x; 1.8683x over previous
#include <cuda_runtime.h>
#include <cstdint>

// ---------------- problem constants ----------------
#define BATCH 256
#define HW    147456            // 384*384 px per sample
#define NB    4096              // histogram bins (bin = q >> 4)
#define QSCALE 65535.0f

// target order-statistic ranks (0-based): q*(n-1) = 14745.5 / 132709.5
#define KL 14745
#define KH 132709

// K1 geometry: 4 blocks/sample, 1024 threads, 36 px/thread (R13-proven: 77.4us)
#define TPB1   1024
#define BPS1   4
#define PXB1   (HW / BPS1)            // 36864 px per block
#define ITER1  (PXB1 / (TPB1 * 4))    // 9 iterations of 4 px

// K5 geometry: 9 blocks/sample, 512 threads, 8 float4 (32 px) per thread
#define TPB5   512
#define F4PT   8
#define PXB5   (TPB5 * F4PT * 4)      // 16384 px per block
#define BPS5   (HW / PXB5)            // 9 blocks per sample

// ---------------- device scratch (static, allocation-free, zero-init) -------
__device__ __align__(16) uint32_t g_xq[BATCH * HW / 2];  // packed u16 means, 75 MB
__device__ __align__(16) int g_hist[BATCH * NB];         // per-sample hist (cleaned by k2)
__device__ float2 g_ab[BATCH];                           // loQ, invQ (u16-value units)

// ---- K1: stream x, channel-mean, quantize u16, write xq, coarse hist -------
__global__ void __launch_bounds__(TPB1) k1_quant_hist(const float* __restrict__ x) {
    __shared__ int sh[NB];
    const int s     = blockIdx.x >> 2;
    const int chunk = blockIdx.x & (BPS1 - 1);
    const int t     = threadIdx.x;

    for (int i = t; i < NB; i += TPB1) sh[i] = 0;
    __syncthreads();

    const int base = s * HW + chunk * PXB1;
    const float4* __restrict__ xin = (const float4*)x;
    const float third = 1.0f / 3.0f;

#pragma unroll 3
    for (int it = 0; it < ITER1; ++it) {
        int p  = base + it * (TPB1 * 4) + t * 4;
        int f4 = (p * 3) >> 2;
        float4 a = __ldcs(xin + f4 + 0);   // stream x: don't pollute L2
        float4 b = __ldcs(xin + f4 + 1);
        float4 c = __ldcs(xin + f4 + 2);

        uint32_t q0 = min((uint32_t)((a.x + a.y + a.z) * third * QSCALE + 0.5f), 65535u);
        uint32_t q1 = min((uint32_t)((a.w + b.x + b.y) * third * QSCALE + 0.5f), 65535u);
        uint32_t q2 = min((uint32_t)((b.z + b.w + c.x) * third * QSCALE + 0.5f), 65535u);
        uint32_t q3 = min((uint32_t)((c.y + c.z + c.w) * third * QSCALE + 0.5f), 65535u);

        uint2 w; w.x = q0 | (q1 << 16); w.y = q2 | (q3 << 16);
        ((uint2*)g_xq)[p >> 2] = w;        // retain in L2 for K5

        atomicAdd(&sh[q0 >> 4], 1);
        atomicAdd(&sh[q1 >> 4], 1);
        atomicAdd(&sh[q2 >> 4], 1);
        atomicAdd(&sh[q3 >> 4], 1);
    }
    __syncthreads();

    int* gh = &g_hist[s * NB];
    for (int i = t; i < NB; i += TPB1) {
        int v = sh[i];
        if (v) atomicAdd(&gh[i], v);       // result unused -> REDG
    }
}

// ---- k2: scan hist, interpolate quantiles within bins, self-clean ----------
__global__ void __launch_bounds__(1024) k2_scan_interp() {
    __shared__ int   s_warp[32];
    __shared__ float s_v[4];
    const int s = blockIdx.x;
    const int t = threadIdx.x;
    const int lane = t & 31;
    const int wid  = t >> 5;

    int* gh = &g_hist[s * NB];
    int4 cw = *(int4*)(gh + 4 * t);
    *(int4*)(gh + 4 * t) = make_int4(0, 0, 0, 0);   // self-clean for graph replay
    int cnt[4] = {cw.x, cw.y, cw.z, cw.w};
    int local = cnt[0] + cnt[1] + cnt[2] + cnt[3];

    int v = local;
#pragma unroll
    for (int o = 1; o < 32; o <<= 1) {
        int n = __shfl_up_sync(0xFFFFFFFFu, v, o);
        if (lane >= o) v += n;
    }
    if (lane == 31) s_warp[wid] = v;
    __syncthreads();
    if (wid == 0) {
        int wv = s_warp[lane];
#pragma unroll
        for (int o = 1; o < 32; o <<= 1) {
            int n = __shfl_up_sync(0xFFFFFFFFu, wv, o);
            if (lane >= o) wv += n;
        }
        s_warp[lane] = wv;
    }
    __syncthreads();
    int cum = (v - local) + (wid ? s_warp[wid - 1] : 0);

    // locate the 4 target ranks; interpolate within bin (u16-value units)
    const int targets[4] = {KL, KL + 1, KH, KH + 1};
    const int base = t * 4;
    const float BW = 16.0f;                // 65536 / 4096 u16-units per bin
#pragma unroll
    for (int i = 0; i < 4; i++) {
        int c = cnt[i];
#pragma unroll
        for (int k = 0; k < 4; k++) {
            int r = targets[k];
            if (cum <= r && r < cum + c)
                s_v[k] = ((float)(base + i) + ((float)(r - cum) + 0.5f) / (float)c) * BW;
        }
        cum += c;
    }
    __syncthreads();

    if (t == 0) {
        float loQ = 0.5f * (s_v[0] + s_v[1]);
        float hiQ = 0.5f * (s_v[2] + s_v[3]);
        float rngQ = fmaxf(hiQ - loQ, 1e-6f * QSCALE);
        g_ab[s] = make_float2(loQ, 1.0f / rngQ);
    }
}

// ---- K5: normalize + clip; xq read mostly L2-hot, streamed output ----------
__global__ void __launch_bounds__(TPB5) k5_norm(float* __restrict__ out) {
    const int s     = blockIdx.x / BPS5;
    const int chunk = blockIdx.x % BPS5;
    const int t     = threadIdx.x;

    float2 ab = g_ab[s];
    const float loQ  = ab.x;
    const float invQ = ab.y;

    const uint2* __restrict__ xq2 =
        (const uint2*)g_xq + (size_t)s * (HW / 4) + chunk * (TPB5 * F4PT);
    float4* __restrict__ o4 =
        (float4*)out + (size_t)s * (HW / 4) + chunk * (TPB5 * F4PT);

#pragma unroll
    for (int k = 0; k < F4PT; k++) {
        uint2 w = __ldcs(xq2 + k * TPB5 + t);   // last use of xq
        float4 r;
        r.x = __saturatef(((float)(w.x & 0xFFFFu) - loQ) * invQ);
        r.y = __saturatef(((float)(w.x >> 16)     - loQ) * invQ);
        r.z = __saturatef(((float)(w.y & 0xFFFFu) - loQ) * invQ);
        r.w = __saturatef(((float)(w.y >> 16)     - loQ) * invQ);
        __stcs(o4 + k * TPB5 + t, r);
    }
}

// ---------------- launch ----------------
extern "C" void kernel_launch(void* const* d_in, const int* in_sizes, int n_in,
                              void* d_out, int out_size) {
    const float* x = (const float*)d_in[0];
    float* out = (float*)d_out;

    k1_quant_hist<<<BATCH * BPS1, TPB1>>>(x);
    k2_scan_interp<<<BATCH, 1024>>>();
    k5_norm<<<BATCH * BPS5, TPB5>>>(out);
}